// round 4
// baseline (speedup 1.0000x reference)
#include <cuda_runtime.h>
#include <math.h>

#define NT 128
#define FR_FLOATS (96 * NT)   // 8 frames * 12 floats per thread

struct V3 { float x, y, z; };

__device__ __forceinline__ V3 vsub(V3 a, V3 b) { return V3{a.x - b.x, a.y - b.y, a.z - b.z}; }
__device__ __forceinline__ V3 vcross(V3 a, V3 b) {
    return V3{a.y * b.z - a.z * b.y, a.z * b.x - a.x * b.z, a.x * b.y - a.y * b.x};
}
__device__ __forceinline__ float vdot(V3 a, V3 b) { return a.x * b.x + a.y * b.y + a.z * b.z; }

// Matches reference _dihedral exactly (including nan_to_num -> 0)
__device__ __forceinline__ float dihedral(V3 p0, V3 p1, V3 p2, V3 p3) {
    V3 b0 = vsub(p0, p1);            // -(p1 - p0)
    V3 b1 = vsub(p2, p1);
    V3 b2 = vsub(p3, p2);
    V3 v1 = vcross(b0, b1);          // b0 x b1
    V3 v2 = vcross(b2, b1);          // cross(b2, b1) per reference
    float y = vdot(vcross(v1, v2), b1) * rsqrtf(vdot(b1, b1));
    float x = vdot(v1, v2);
    float a = atan2f(y, x);
    return (a != a) ? 0.0f : a;      // nan_to_num
}

__global__ void __launch_bounds__(NT)
idealizer_kernel(const int* __restrict__ aa,
                 const float* __restrict__ bb,      // [n,4,3]
                 const float* __restrict__ tor,     // [n,4]
                 const float* __restrict__ dfr,     // [21,8,4,4]
                 const int* __restrict__ gidx,      // [21,14]
                 const float* __restrict__ amask,   // [21,14]
                 const float* __restrict__ lit,     // [21,14,3]
                 float* __restrict__ out,           // [n,14,3]
                 int n)
{
    extern __shared__ float smem[];  // 96*NT floats: frames, later reused as output staging
    const int tid = threadIdx.x;
    const int base = blockIdx.x * NT;
    const int i = base + tid;
    const bool active = i < n;

    float bbv[12];
    float pred[30];

    if (active) {
        const float4* b4 = reinterpret_cast<const float4*>(bb) + (size_t)i * 3;
        float4 q0 = b4[0], q1 = b4[1], q2 = b4[2];
        bbv[0] = q0.x; bbv[1] = q0.y; bbv[2]  = q0.z; bbv[3]  = q0.w;
        bbv[4] = q1.x; bbv[5] = q1.y; bbv[6]  = q1.z; bbv[7]  = q1.w;
        bbv[8] = q2.x; bbv[9] = q2.y; bbv[10] = q2.z; bbv[11] = q2.w;
        V3 Nv  = {bbv[0], bbv[1], bbv[2]};
        V3 CAv = {bbv[3], bbv[4], bbv[5]};
        V3 Cv  = {bbv[6], bbv[7], bbv[8]};

        // ---- dihedrals: angles = [omega, phi, psi, sc0..3] ----
        float ang[7];
        if (i + 1 < n) {
            const float* nb = bb + (size_t)(i + 1) * 12;
            V3 Nn  = {nb[0], nb[1], nb[2]};
            V3 CAn = {nb[3], nb[4], nb[5]};
            ang[0] = dihedral(CAv, Cv, Nn, CAn);   // omega
            ang[2] = dihedral(Nv, CAv, Cv, Nn);    // psi
        } else { ang[0] = 0.f; ang[2] = 0.f; }
        if (i > 0) {
            const float* pb = bb + (size_t)(i - 1) * 12;
            V3 Cp = {pb[6], pb[7], pb[8]};
            ang[1] = dihedral(Cp, Nv, CAv, Cv);    // phi
        } else { ang[1] = 0.f; }
        {
            const float4 t4 = reinterpret_cast<const float4*>(tor)[i];
            ang[3] = t4.x; ang[4] = t4.y; ang[5] = t4.z; ang[6] = t4.w;
        }

        // ---- backbone frame from reference (N, CA, C) ----
        V3 nrel = vsub(Nv, CAv);
        V3 crel = vsub(Cv, CAv);
        const float eps = 1e-20f;
        float txy = crel.x * crel.x + crel.y * crel.y;
        float i1 = rsqrtf(eps + txy);
        float s1 = -crel.y * i1, c1 = crel.x * i1;
        float i2 = rsqrtf(eps + txy + crel.z * crel.z);
        float s2 = crel.z * i2, c2 = sqrtf(txy) * i2;
        // Rc = R2 @ R1
        float Rc00 =  c2 * c1, Rc01 = -c2 * s1, Rc02 = s2;
        float Rc10 =  s1,      Rc11 =  c1;      // Rc12 = 0
        float Rc20 = -s2 * c1, Rc21 =  s2 * s1, Rc22 = c2;
        float n2y = Rc10 * nrel.x + Rc11 * nrel.y;
        float n2z = Rc20 * nrel.x + Rc21 * nrel.y + Rc22 * nrel.z;
        float i3 = rsqrtf(eps + n2y * n2y + n2z * n2z);
        float sn = -n2z * i3, cn = n2y * i3;
        // M = Rn @ Rc ; backbone rotation bb_r = M^T
        float M00 = Rc00, M01 = Rc01, M02 = Rc02;
        float M10 = cn * Rc10 - sn * Rc20;
        float M11 = cn * Rc11 - sn * Rc21;
        float M12 = -sn * Rc22;
        float M20 = sn * Rc10 + cn * Rc20;
        float M21 = sn * Rc11 + cn * Rc21;
        float M22 = cn * Rc22;

        const int a_i = aa[i];
        const float4* df = reinterpret_cast<const float4*>(dfr) + (size_t)a_i * 32;
        float rr[9], rt[3];   // running composed chain frame

        #pragma unroll
        for (int k = 0; k < 8; k++) {
            float4 r0  = __ldg(df + k * 4 + 0);
            float4 r1  = __ldg(df + k * 4 + 1);
            float4 r2v = __ldg(df + k * 4 + 2);
            float s, c;
            if (k == 0) { s = 0.f; c = 1.f; }
            else { sincosf(ang[k - 1], &s, &c); }
            // fr = dr @ Ra ; Ra rotates about x: col1' = c*col1 + s*col2, col2' = -s*col1 + c*col2
            float f00 = r0.x,  f01 = c * r0.y + s * r0.z,  f02 = -s * r0.y + c * r0.z;
            float f10 = r1.x,  f11 = c * r1.y + s * r1.z,  f12 = -s * r1.y + c * r1.z;
            float f20 = r2v.x, f21 = c * r2v.y + s * r2v.z, f22 = -s * r2v.y + c * r2v.z;
            float ft0 = r0.w, ft1 = r1.w, ft2 = r2v.w;

            float c00, c01, c02, c10, c11, c12, c20, c21, c22, ct0, ct1, ct2;
            if (k <= 4) {
                c00 = f00; c01 = f01; c02 = f02;
                c10 = f10; c11 = f11; c12 = f12;
                c20 = f20; c21 = f21; c22 = f22;
                ct0 = ft0; ct1 = ft1; ct2 = ft2;
                if (k == 4) {
                    rr[0]=f00; rr[1]=f01; rr[2]=f02; rr[3]=f10; rr[4]=f11; rr[5]=f12;
                    rr[6]=f20; rr[7]=f21; rr[8]=f22; rt[0]=ft0; rt[1]=ft1; rt[2]=ft2;
                }
            } else {
                // (rr,rt) = compose(rr,rt, f,ft): r' = rr@f, t' = rr@ft + rt
                float n00 = rr[0]*f00 + rr[1]*f10 + rr[2]*f20;
                float n01 = rr[0]*f01 + rr[1]*f11 + rr[2]*f21;
                float n02 = rr[0]*f02 + rr[1]*f12 + rr[2]*f22;
                float n10 = rr[3]*f00 + rr[4]*f10 + rr[5]*f20;
                float n11 = rr[3]*f01 + rr[4]*f11 + rr[5]*f21;
                float n12 = rr[3]*f02 + rr[4]*f12 + rr[5]*f22;
                float n20 = rr[6]*f00 + rr[7]*f10 + rr[8]*f20;
                float n21 = rr[6]*f01 + rr[7]*f11 + rr[8]*f21;
                float n22 = rr[6]*f02 + rr[7]*f12 + rr[8]*f22;
                float nt0 = rr[0]*ft0 + rr[1]*ft1 + rr[2]*ft2 + rt[0];
                float nt1 = rr[3]*ft0 + rr[4]*ft1 + rr[5]*ft2 + rt[1];
                float nt2 = rr[6]*ft0 + rr[7]*ft1 + rr[8]*ft2 + rt[2];
                rr[0]=n00; rr[1]=n01; rr[2]=n02; rr[3]=n10; rr[4]=n11; rr[5]=n12;
                rr[6]=n20; rr[7]=n21; rr[8]=n22; rt[0]=nt0; rt[1]=nt1; rt[2]=nt2;
                c00=n00; c01=n01; c02=n02; c10=n10; c11=n11; c12=n12;
                c20=n20; c21=n21; c22=n22; ct0=nt0; ct1=nt1; ct2=nt2;
            }
            // Global frame: G = bb_r @ c ; bb_r[r][m] = M[m][r]
            float G00 = M00*c00 + M10*c10 + M20*c20;
            float G01 = M00*c01 + M10*c11 + M20*c21;
            float G02 = M00*c02 + M10*c12 + M20*c22;
            float G10 = M01*c00 + M11*c10 + M21*c20;
            float G11 = M01*c01 + M11*c11 + M21*c21;
            float G12 = M01*c02 + M11*c12 + M21*c22;
            float G20 = M02*c00 + M12*c10 + M22*c20;
            float G21 = M02*c01 + M12*c11 + M22*c21;
            float G22 = M02*c02 + M12*c12 + M22*c22;
            float Gt0 = M00*ct0 + M10*ct1 + M20*ct2 + CAv.x;
            float Gt1 = M01*ct0 + M11*ct1 + M21*ct2 + CAv.y;
            float Gt2 = M02*ct0 + M12*ct1 + M22*ct2 + CAv.z;

            int kb = k * 12;
            smem[(kb + 0) * NT + tid] = G00;
            smem[(kb + 1) * NT + tid] = G01;
            smem[(kb + 2) * NT + tid] = G02;
            smem[(kb + 3) * NT + tid] = G10;
            smem[(kb + 4) * NT + tid] = G11;
            smem[(kb + 5) * NT + tid] = G12;
            smem[(kb + 6) * NT + tid] = G20;
            smem[(kb + 7) * NT + tid] = G21;
            smem[(kb + 8) * NT + tid] = G22;
            smem[(kb + 9) * NT + tid] = Gt0;
            smem[(kb + 10) * NT + tid] = Gt1;
            smem[(kb + 11) * NT + tid] = Gt2;
        }

        // ---- atoms 4..13 ----
        #pragma unroll
        for (int a = 0; a < 10; a++) {
            int ai = a_i * 14 + (a + 4);
            int g = __ldg(gidx + ai);
            float m = __ldg(amask + ai);
            float lx = __ldg(lit + (size_t)ai * 3 + 0);
            float ly = __ldg(lit + (size_t)ai * 3 + 1);
            float lz = __ldg(lit + (size_t)ai * 3 + 2);
            int gb = g * 12;
            float G00 = smem[(gb + 0) * NT + tid];
            float G01 = smem[(gb + 1) * NT + tid];
            float G02 = smem[(gb + 2) * NT + tid];
            float G10 = smem[(gb + 3) * NT + tid];
            float G11 = smem[(gb + 4) * NT + tid];
            float G12 = smem[(gb + 5) * NT + tid];
            float G20 = smem[(gb + 6) * NT + tid];
            float G21 = smem[(gb + 7) * NT + tid];
            float G22 = smem[(gb + 8) * NT + tid];
            float Gt0 = smem[(gb + 9) * NT + tid];
            float Gt1 = smem[(gb + 10) * NT + tid];
            float Gt2 = smem[(gb + 11) * NT + tid];
            pred[a * 3 + 0] = (G00 * lx + G01 * ly + G02 * lz + Gt0) * m;
            pred[a * 3 + 1] = (G10 * lx + G11 * ly + G12 * lz + Gt1) * m;
            pred[a * 3 + 2] = (G20 * lx + G21 * ly + G22 * lz + Gt2) * m;
        }
    }

    // ---- staged, coalesced output ----
    __syncthreads();   // everyone done reading their frames from smem
    if (active) {
        float* st = smem + tid * 42;
        #pragma unroll
        for (int j = 0; j < 12; j++) st[j] = bbv[j];
        #pragma unroll
        for (int j = 0; j < 30; j++) st[12 + j] = pred[j];
    }
    __syncthreads();

    int nvalid = n - base; if (nvalid > NT) nvalid = NT;
    int total = nvalid * 42;
    float* gout = out + (size_t)base * 42;
    int total4 = total >> 2;
    const float4* s4 = reinterpret_cast<const float4*>(smem);
    float4* g4 = reinterpret_cast<float4*>(gout);
    for (int idx = tid; idx < total4; idx += NT) g4[idx] = s4[idx];
    for (int idx = (total4 << 2) + tid; idx < total; idx += NT) gout[idx] = smem[idx];
}

extern "C" void kernel_launch(void* const* d_in, const int* in_sizes, int n_in,
                              void* d_out, int out_size) {
    const int*   aa    = (const int*)d_in[0];
    const float* bb    = (const float*)d_in[1];
    const float* tor   = (const float*)d_in[2];
    const float* dfr   = (const float*)d_in[3];
    const int*   gidx  = (const int*)d_in[4];
    const float* amask = (const float*)d_in[5];
    const float* lit   = (const float*)d_in[6];
    float* out = (float*)d_out;

    int n = in_sizes[0];
    int grid = (n + NT - 1) / NT;
    size_t smem_bytes = (size_t)FR_FLOATS * sizeof(float);   // 49152 = 48KB
    idealizer_kernel<<<grid, NT, smem_bytes>>>(aa, bb, tor, dfr, gidx, amask, lit, out, n);
}

// round 5
// speedup vs baseline: 1.3576x; 1.3576x over previous
#include <cuda_runtime.h>
#include <math.h>

#define NT 256
#define DF_STRIDE 97          // 96 floats per aa row + 1 pad (odd -> conflict-free across aa)
#define AT_STRIDE 51          // 10 atoms * 5 floats + 1 pad (odd)
#define FR_FLOATS (96 * NT)   // 8 frames * 12 floats per thread
#define DF_FLOATS (21 * DF_STRIDE)
#define AT_FLOATS (21 * AT_STRIDE)
#define SMEM_FLOATS (FR_FLOATS + DF_FLOATS + AT_FLOATS)

struct V3 { float x, y, z; };

__device__ __forceinline__ V3 vsub(V3 a, V3 b) { return V3{a.x - b.x, a.y - b.y, a.z - b.z}; }
__device__ __forceinline__ V3 vcross(V3 a, V3 b) {
    return V3{a.y * b.z - a.z * b.y, a.z * b.x - a.x * b.z, a.x * b.y - a.y * b.x};
}
__device__ __forceinline__ float vdot(V3 a, V3 b) { return a.x * b.x + a.y * b.y + a.z * b.z; }

// Matches reference _dihedral exactly (including nan_to_num -> 0)
__device__ __forceinline__ float dihedral(V3 p0, V3 p1, V3 p2, V3 p3) {
    V3 b0 = vsub(p0, p1);            // -(p1 - p0)
    V3 b1 = vsub(p2, p1);
    V3 b2 = vsub(p3, p2);
    V3 v1 = vcross(b0, b1);          // b0 x b1
    V3 v2 = vcross(b2, b1);          // cross(b2, b1) per reference
    float y = vdot(vcross(v1, v2), b1) * rsqrtf(vdot(b1, b1));
    float x = vdot(v1, v2);
    float a = atan2f(y, x);
    return (a != a) ? 0.0f : a;      // nan_to_num
}

__global__ void __launch_bounds__(NT)
idealizer_kernel(const int* __restrict__ aa,
                 const float* __restrict__ bb,      // [n,4,3]
                 const float* __restrict__ tor,     // [n,4]
                 const float* __restrict__ dfr,     // [21,8,4,4]
                 const int* __restrict__ gidx,      // [21,14]
                 const float* __restrict__ amask,   // [21,14]
                 const float* __restrict__ lit,     // [21,14,3]
                 float* __restrict__ out,           // [n,14,3]
                 int n)
{
    extern __shared__ float smem[];
    float* fr_s = smem;                 // frames [comp 0..95][tid]; first 12 rows double as bb staging
    float* df_s = smem + FR_FLOATS;     // [21][97]
    float* at_s = df_s + DF_FLOATS;     // [21][51]

    const int tid = threadIdx.x;
    const int base = blockIdx.x * NT;
    const int i = base + tid;
    const bool active = i < n;

    float bbv[12];
    float t4x, t4y, t4z, t4w;
    int a_i = 0;

    if (active) {
        const float4* b4 = reinterpret_cast<const float4*>(bb) + (size_t)i * 3;
        float4 q0 = b4[0], q1 = b4[1], q2 = b4[2];
        bbv[0] = q0.x; bbv[1] = q0.y; bbv[2]  = q0.z; bbv[3]  = q0.w;
        bbv[4] = q1.x; bbv[5] = q1.y; bbv[6]  = q1.z; bbv[7]  = q1.w;
        bbv[8] = q2.x; bbv[9] = q2.y; bbv[10] = q2.z; bbv[11] = q2.w;
        const float4 t4 = reinterpret_cast<const float4*>(tor)[i];
        t4x = t4.x; t4y = t4.y; t4z = t4.z; t4w = t4.w;
        a_i = aa[i];
        // stage bb for neighbor dihedral reads
        #pragma unroll
        for (int c = 0; c < 12; c++) fr_s[c * NT + tid] = bbv[c];
    }

    // ---- cooperative table loads into padded smem ----
    // default frames: 21 aa * 8 frames * 12 floats (rows 0..2 of each 4x4)
    for (int idx = tid; idx < 21 * 96; idx += NT) {
        int a = idx / 96;
        int r = idx - a * 96;                   // r = k*12 + j, j = row*4+col (row<3)
        int k = r / 12;
        int j = r - k * 12;
        df_s[a * DF_STRIDE + r] = __ldg(dfr + a * 128 + k * 16 + j);
    }
    // atom records: 21 aa * 10 atoms * {gidx, mask, lit.xyz}
    for (int idx = tid; idx < 21 * 10; idx += NT) {
        int a = idx / 10;
        int at = idx - a * 10;                  // atom at+4
        int ai = a * 14 + at + 4;
        float* dst = at_s + a * AT_STRIDE + at * 5;
        dst[0] = __int_as_float(__ldg(gidx + ai));
        dst[1] = __ldg(amask + ai);
        dst[2] = __ldg(lit + (size_t)ai * 3 + 0);
        dst[3] = __ldg(lit + (size_t)ai * 3 + 1);
        dst[4] = __ldg(lit + (size_t)ai * 3 + 2);
    }
    __syncthreads();

    float ang[7];
    float M00, M01, M02, M10, M11, M12, M20, M21, M22;
    V3 CAv;

    if (active) {
        V3 Nv  = {bbv[0], bbv[1], bbv[2]};
        CAv    = {bbv[3], bbv[4], bbv[5]};
        V3 Cv  = {bbv[6], bbv[7], bbv[8]};

        // ---- dihedrals: angles = [omega, phi, psi, sc0..3], neighbors from smem ----
        if (i + 1 < n) {
            V3 Nn, CAn;
            if (tid < NT - 1) {
                Nn  = {fr_s[0 * NT + tid + 1], fr_s[1 * NT + tid + 1], fr_s[2 * NT + tid + 1]};
                CAn = {fr_s[3 * NT + tid + 1], fr_s[4 * NT + tid + 1], fr_s[5 * NT + tid + 1]};
            } else {
                const float* nb = bb + (size_t)(i + 1) * 12;
                Nn  = {nb[0], nb[1], nb[2]};
                CAn = {nb[3], nb[4], nb[5]};
            }
            ang[0] = dihedral(CAv, Cv, Nn, CAn);   // omega
            ang[2] = dihedral(Nv, CAv, Cv, Nn);    // psi
        } else { ang[0] = 0.f; ang[2] = 0.f; }
        if (i > 0) {
            V3 Cp;
            if (tid > 0) {
                Cp = {fr_s[6 * NT + tid - 1], fr_s[7 * NT + tid - 1], fr_s[8 * NT + tid - 1]};
            } else {
                const float* pb = bb + (size_t)(i - 1) * 12;
                Cp = {pb[6], pb[7], pb[8]};
            }
            ang[1] = dihedral(Cp, Nv, CAv, Cv);    // phi
        } else { ang[1] = 0.f; }
        ang[3] = t4x; ang[4] = t4y; ang[5] = t4z; ang[6] = t4w;

        // ---- backbone frame from reference (N, CA, C) ----
        V3 nrel = vsub(Nv, CAv);
        V3 crel = vsub(Cv, CAv);
        const float eps = 1e-20f;
        float txy = crel.x * crel.x + crel.y * crel.y;
        float i1 = rsqrtf(eps + txy);
        float s1 = -crel.y * i1, c1 = crel.x * i1;
        float i2 = rsqrtf(eps + txy + crel.z * crel.z);
        float s2 = crel.z * i2, c2 = sqrtf(txy) * i2;
        // Rc = R2 @ R1
        float Rc00 =  c2 * c1, Rc01 = -c2 * s1, Rc02 = s2;
        float Rc10 =  s1,      Rc11 =  c1;      // Rc12 = 0
        float Rc20 = -s2 * c1, Rc21 =  s2 * s1, Rc22 = c2;
        float n2y = Rc10 * nrel.x + Rc11 * nrel.y;
        float n2z = Rc20 * nrel.x + Rc21 * nrel.y + Rc22 * nrel.z;
        float i3 = rsqrtf(eps + n2y * n2y + n2z * n2z);
        float sn = -n2z * i3, cn = n2y * i3;
        // M = Rn @ Rc ; backbone rotation bb_r = M^T
        M00 = Rc00; M01 = Rc01; M02 = Rc02;
        M10 = cn * Rc10 - sn * Rc20;
        M11 = cn * Rc11 - sn * Rc21;
        M12 = -sn * Rc22;
        M20 = sn * Rc10 + cn * Rc20;
        M21 = sn * Rc11 + cn * Rc21;
        M22 = cn * Rc22;
    }

    __syncthreads();   // all neighbor reads of bb staging done; frames may now overwrite rows 0..11

    float pred[30];
    if (active) {
        const float* dfa = df_s + a_i * DF_STRIDE;
        float rr[9], rt[3];   // running composed chain frame

        #pragma unroll
        for (int k = 0; k < 8; k++) {
            float d[12];
            #pragma unroll
            for (int j = 0; j < 12; j++) d[j] = dfa[k * 12 + j];
            float s, c;
            if (k == 0) { s = 0.f; c = 1.f; }
            else { __sincosf(ang[k - 1], &s, &c); }
            // fr = dr @ Ra ; Ra rotates about x: col1' = c*col1 + s*col2, col2' = -s*col1 + c*col2
            float f00 = d[0], f01 = c * d[1] + s * d[2],  f02 = -s * d[1] + c * d[2];
            float f10 = d[4], f11 = c * d[5] + s * d[6],  f12 = -s * d[5] + c * d[6];
            float f20 = d[8], f21 = c * d[9] + s * d[10], f22 = -s * d[9] + c * d[10];
            float ft0 = d[3], ft1 = d[7], ft2 = d[11];

            float c00, c01, c02, c10, c11, c12, c20, c21, c22, ct0, ct1, ct2;
            if (k <= 4) {
                c00 = f00; c01 = f01; c02 = f02;
                c10 = f10; c11 = f11; c12 = f12;
                c20 = f20; c21 = f21; c22 = f22;
                ct0 = ft0; ct1 = ft1; ct2 = ft2;
                if (k == 4) {
                    rr[0]=f00; rr[1]=f01; rr[2]=f02; rr[3]=f10; rr[4]=f11; rr[5]=f12;
                    rr[6]=f20; rr[7]=f21; rr[8]=f22; rt[0]=ft0; rt[1]=ft1; rt[2]=ft2;
                }
            } else {
                // (rr,rt) = compose(rr,rt, f,ft): r' = rr@f, t' = rr@ft + rt
                float n00 = rr[0]*f00 + rr[1]*f10 + rr[2]*f20;
                float n01 = rr[0]*f01 + rr[1]*f11 + rr[2]*f21;
                float n02 = rr[0]*f02 + rr[1]*f12 + rr[2]*f22;
                float n10 = rr[3]*f00 + rr[4]*f10 + rr[5]*f20;
                float n11 = rr[3]*f01 + rr[4]*f11 + rr[5]*f21;
                float n12 = rr[3]*f02 + rr[4]*f12 + rr[5]*f22;
                float n20 = rr[6]*f00 + rr[7]*f10 + rr[8]*f20;
                float n21 = rr[6]*f01 + rr[7]*f11 + rr[8]*f21;
                float n22 = rr[6]*f02 + rr[7]*f12 + rr[8]*f22;
                float nt0 = rr[0]*ft0 + rr[1]*ft1 + rr[2]*ft2 + rt[0];
                float nt1 = rr[3]*ft0 + rr[4]*ft1 + rr[5]*ft2 + rt[1];
                float nt2 = rr[6]*ft0 + rr[7]*ft1 + rr[8]*ft2 + rt[2];
                rr[0]=n00; rr[1]=n01; rr[2]=n02; rr[3]=n10; rr[4]=n11; rr[5]=n12;
                rr[6]=n20; rr[7]=n21; rr[8]=n22; rt[0]=nt0; rt[1]=nt1; rt[2]=nt2;
                c00=n00; c01=n01; c02=n02; c10=n10; c11=n11; c12=n12;
                c20=n20; c21=n21; c22=n22; ct0=nt0; ct1=nt1; ct2=nt2;
            }
            // Global frame: G = bb_r @ c ; bb_r[r][m] = M[m][r]
            float G00 = M00*c00 + M10*c10 + M20*c20;
            float G01 = M00*c01 + M10*c11 + M20*c21;
            float G02 = M00*c02 + M10*c12 + M20*c22;
            float G10 = M01*c00 + M11*c10 + M21*c20;
            float G11 = M01*c01 + M11*c11 + M21*c21;
            float G12 = M01*c02 + M11*c12 + M21*c22;
            float G20 = M02*c00 + M12*c10 + M22*c20;
            float G21 = M02*c01 + M12*c11 + M22*c21;
            float G22 = M02*c02 + M12*c12 + M22*c22;
            float Gt0 = M00*ct0 + M10*ct1 + M20*ct2 + CAv.x;
            float Gt1 = M01*ct0 + M11*ct1 + M21*ct2 + CAv.y;
            float Gt2 = M02*ct0 + M12*ct1 + M22*ct2 + CAv.z;

            int kb = k * 12;
            fr_s[(kb + 0) * NT + tid] = G00;
            fr_s[(kb + 1) * NT + tid] = G01;
            fr_s[(kb + 2) * NT + tid] = G02;
            fr_s[(kb + 3) * NT + tid] = G10;
            fr_s[(kb + 4) * NT + tid] = G11;
            fr_s[(kb + 5) * NT + tid] = G12;
            fr_s[(kb + 6) * NT + tid] = G20;
            fr_s[(kb + 7) * NT + tid] = G21;
            fr_s[(kb + 8) * NT + tid] = G22;
            fr_s[(kb + 9) * NT + tid] = Gt0;
            fr_s[(kb + 10) * NT + tid] = Gt1;
            fr_s[(kb + 11) * NT + tid] = Gt2;
        }

        // ---- atoms 4..13 ----
        const float* ata = at_s + a_i * AT_STRIDE;
        #pragma unroll
        for (int a = 0; a < 10; a++) {
            int g   = __float_as_int(ata[a * 5 + 0]);
            float m = ata[a * 5 + 1];
            float lx = ata[a * 5 + 2];
            float ly = ata[a * 5 + 3];
            float lz = ata[a * 5 + 4];
            int gb = g * 12;
            float G00 = fr_s[(gb + 0) * NT + tid];
            float G01 = fr_s[(gb + 1) * NT + tid];
            float G02 = fr_s[(gb + 2) * NT + tid];
            float G10 = fr_s[(gb + 3) * NT + tid];
            float G11 = fr_s[(gb + 4) * NT + tid];
            float G12 = fr_s[(gb + 5) * NT + tid];
            float G20 = fr_s[(gb + 6) * NT + tid];
            float G21 = fr_s[(gb + 7) * NT + tid];
            float G22 = fr_s[(gb + 8) * NT + tid];
            float Gt0 = fr_s[(gb + 9) * NT + tid];
            float Gt1 = fr_s[(gb + 10) * NT + tid];
            float Gt2 = fr_s[(gb + 11) * NT + tid];
            pred[a * 3 + 0] = (G00 * lx + G01 * ly + G02 * lz + Gt0) * m;
            pred[a * 3 + 1] = (G10 * lx + G11 * ly + G12 * lz + Gt1) * m;
            pred[a * 3 + 2] = (G20 * lx + G21 * ly + G22 * lz + Gt2) * m;
        }
    }

    // ---- staged, coalesced output (stride 43 -> conflict-free STS) ----
    __syncthreads();   // everyone done reading their frames from smem
    if (active) {
        float* st = smem + tid * 43;
        #pragma unroll
        for (int j = 0; j < 12; j++) st[j] = bbv[j];
        #pragma unroll
        for (int j = 0; j < 30; j++) st[12 + j] = pred[j];
    }
    __syncthreads();

    int nvalid = n - base; if (nvalid > NT) nvalid = NT;
    int total = nvalid * 42;
    float* gout = out + (size_t)base * 42;
    int total4 = total >> 2;
    float4* g4 = reinterpret_cast<float4*>(gout);
    for (int idx = tid; idx < total4; idx += NT) {
        int b = idx << 2;
        float4 v;
        #pragma unroll
        for (int e = 0; e < 4; e++) {
            int bi = b + e;
            int r = bi / 42;
            int c = bi - r * 42;
            (&v.x)[e] = smem[r * 43 + c];
        }
        g4[idx] = v;
    }
    for (int idx = (total4 << 2) + tid; idx < total; idx += NT) {
        int r = idx / 42;
        int c = idx - r * 42;
        gout[idx] = smem[r * 43 + c];
    }
}

extern "C" void kernel_launch(void* const* d_in, const int* in_sizes, int n_in,
                              void* d_out, int out_size) {
    const int*   aa    = (const int*)d_in[0];
    const float* bb    = (const float*)d_in[1];
    const float* tor   = (const float*)d_in[2];
    const float* dfr   = (const float*)d_in[3];
    const int*   gidx  = (const int*)d_in[4];
    const float* amask = (const float*)d_in[5];
    const float* lit   = (const float*)d_in[6];
    float* out = (float*)d_out;

    int n = in_sizes[0];
    int grid = (n + NT - 1) / NT;
    size_t smem_bytes = (size_t)SMEM_FLOATS * sizeof(float);   // ~110.7 KB
    cudaFuncSetAttribute(idealizer_kernel, cudaFuncAttributeMaxDynamicSharedMemorySize,
                         (int)smem_bytes);
    idealizer_kernel<<<grid, NT, smem_bytes>>>(aa, bb, tor, dfr, gidx, amask, lit, out, n);
}